// round 15
// baseline (speedup 1.0000x reference)
#include <cuda_runtime.h>

#define NFFT   16384
#define LOGN   14
#define LSEQ   8192
#define NT     1024
#define DCH    256
#define NROWS  2048

typedef unsigned long long u64;

// ---- packed f32x2 add/sub (sm_103a; ptxas never emits these from C++) ----
__device__ __forceinline__ float2 padd(float2 a, float2 b) {
    float2 r;
    asm("add.rn.f32x2 %0, %1, %2;"
        : "=l"(reinterpret_cast<u64&>(r))
        : "l"(reinterpret_cast<u64&>(a)), "l"(reinterpret_cast<u64&>(b)));
    return r;
}
__device__ __forceinline__ float2 psub(float2 a, float2 b) {
    float2 r;
    asm("sub.rn.f32x2 %0, %1, %2;"
        : "=l"(reinterpret_cast<u64&>(r))
        : "l"(reinterpret_cast<u64&>(a)), "l"(reinterpret_cast<u64&>(b)));
    return r;
}

// scalar complex multiply (round-10 showed packed fma here is a LOSS)
__device__ __forceinline__ float2 cmul(float2 a, float2 b) {
    return make_float2(fmaf(a.x, b.x, -a.y * b.y), fmaf(a.x, b.y, a.y * b.x));
}
// a * conj(b)
__device__ __forceinline__ float2 cmulc(float2 a, float2 b) {
    return make_float2(fmaf(a.x, b.x,  a.y * b.y), fmaf(a.y, b.x, -a.x * b.y));
}
__device__ __forceinline__ float2 mi(float2 z) { return make_float2(z.y, -z.x); }  // z * (-i)
__device__ __forceinline__ int sw(int i) { return i ^ ((i >> 4) & 15); }

// 16-byte async copy global -> shared (LDGSTS)
__device__ __forceinline__ void cp16(void* smem_dst, const void* gsrc) {
    unsigned sa = (unsigned)__cvta_generic_to_shared(smem_dst);
    asm volatile("cp.async.cg.shared.global [%0], [%1], 16;" :: "r"(sa), "l"(gsrc));
}

#define C16_1 make_float2(0.923879532511286756f, -0.382683432365089772f)
#define C16_2 make_float2(0.707106781186547524f, -0.707106781186547524f)
#define C16_3 make_float2(0.382683432365089772f, -0.923879532511286756f)

// DIF butterfly: a' = a+b ; b' = (a-b)*tw
__device__ __forceinline__ void bf(float2& a, float2& b, float2 tw) {
    float2 s = padd(a, b);
    float2 d = psub(a, b);
    a = s; b = cmul(d, tw);
}
// DIT butterfly: t = b*conj(tw) ; a' = a+t ; b' = a-t
__device__ __forceinline__ void bfi(float2& a, float2& b, float2 tw) {
    float2 t = cmulc(b, tw);
    float2 s = padd(a, t);
    b = psub(a, t);
    a = s;
}

// Forward stages at local distances 4, 2, 1 (shared tail of a radix-16 group).
__device__ __forceinline__ void dif_stages123(float2 v[16], float2 ws2) {
    float2 u = cmul(ws2, C16_2);
    bf(v[0], v[4],  ws2); bf(v[1], v[5],  u); bf(v[2],  v[6],  mi(ws2)); bf(v[3],  v[7],  mi(u));
    bf(v[8], v[12], ws2); bf(v[9], v[13], u); bf(v[10], v[14], mi(ws2)); bf(v[11], v[15], mi(u));
    float2 ws4 = cmul(ws2, ws2);
    #pragma unroll
    for (int b = 0; b < 4; b++) {
        bf(v[4*b],   v[4*b+2], ws4);
        bf(v[4*b+1], v[4*b+3], mi(ws4));
    }
    float2 ws8 = cmul(ws4, ws4);
    #pragma unroll
    for (int b = 0; b < 8; b++) bf(v[2*b], v[2*b+1], ws8);
}

// Full 4-stage forward group, base twiddle w (distances 8,4,2,1).
__device__ __forceinline__ void dif4(float2 v[16], float2 w) {
    float2 w1 = cmul(w, C16_1), w2 = cmul(w, C16_2), w3 = cmul(w, C16_3);
    bf(v[0], v[8],  w);     bf(v[1], v[9],  w1);     bf(v[2], v[10], w2);     bf(v[3], v[11], w3);
    bf(v[4], v[12], mi(w)); bf(v[5], v[13], mi(w1)); bf(v[6], v[14], mi(w2)); bf(v[7], v[15], mi(w3));
    dif_stages123(v, cmul(w, w));
}

// First forward group with v[8..15] == 0 (zero-padding): stage 0 degenerates.
__device__ __forceinline__ void dif4_zero(float2 v[16], float2 w) {
    float2 w1 = cmul(w, C16_1), w2 = cmul(w, C16_2), w3 = cmul(w, C16_3);
    v[8]  = cmul(v[0], w);      v[9]  = cmul(v[1], w1);
    v[10] = cmul(v[2], w2);     v[11] = cmul(v[3], w3);
    v[12] = cmul(v[4], mi(w));  v[13] = cmul(v[5], mi(w1));
    v[14] = cmul(v[6], mi(w2)); v[15] = cmul(v[7], mi(w3));
    dif_stages123(v, cmul(w, w));
}

// Full 4-stage inverse group, base twiddle w (distances 1,2,4,8), conj twiddles.
__device__ __forceinline__ void dit4(float2 v[16], float2 w) {
    float2 ws2 = cmul(w, w), ws4 = cmul(ws2, ws2), ws8 = cmul(ws4, ws4);
    #pragma unroll
    for (int b = 0; b < 8; b++) bfi(v[2*b], v[2*b+1], ws8);
    #pragma unroll
    for (int b = 0; b < 4; b++) {
        bfi(v[4*b],   v[4*b+2], ws4);
        bfi(v[4*b+1], v[4*b+3], mi(ws4));
    }
    float2 u = cmul(ws2, C16_2);
    bfi(v[0], v[4],  ws2); bfi(v[1], v[5],  u); bfi(v[2],  v[6],  mi(ws2)); bfi(v[3],  v[7],  mi(u));
    bfi(v[8], v[12], ws2); bfi(v[9], v[13], u); bfi(v[10], v[14], mi(ws2)); bfi(v[11], v[15], mi(u));
    float2 w1 = cmul(w, C16_1), w2 = cmul(w, C16_2), w3 = cmul(w, C16_3);
    bfi(v[0], v[8],  w);     bfi(v[1], v[9],  w1);     bfi(v[2], v[10], w2);     bfi(v[3], v[11], w3);
    bfi(v[4], v[12], mi(w)); bfi(v[5], v[13], mi(w1)); bfi(v[6], v[14], mi(w2)); bfi(v[7], v[15], mi(w3));
}

// Same but last stage (dist 8) emits ONLY the "+" half v[0..7] — the "-"
// outputs map to positions >= 8192 which are discarded.
__device__ __forceinline__ void dit4_half(float2 v[16], float2 w) {
    float2 ws2 = cmul(w, w), ws4 = cmul(ws2, ws2), ws8 = cmul(ws4, ws4);
    #pragma unroll
    for (int b = 0; b < 8; b++) bfi(v[2*b], v[2*b+1], ws8);
    #pragma unroll
    for (int b = 0; b < 4; b++) {
        bfi(v[4*b],   v[4*b+2], ws4);
        bfi(v[4*b+1], v[4*b+3], mi(ws4));
    }
    float2 u = cmul(ws2, C16_2);
    bfi(v[0], v[4],  ws2); bfi(v[1], v[5],  u); bfi(v[2],  v[6],  mi(ws2)); bfi(v[3],  v[7],  mi(u));
    bfi(v[8], v[12], ws2); bfi(v[9], v[13], u); bfi(v[10], v[14], mi(ws2)); bfi(v[11], v[15], mi(u));
    float2 w1 = cmul(w, C16_1), w2 = cmul(w, C16_2), w3 = cmul(w, C16_3);
    v[0] = padd(v[0], cmulc(v[8],  w));
    v[1] = padd(v[1], cmulc(v[9],  w1));
    v[2] = padd(v[2], cmulc(v[10], w2));
    v[3] = padd(v[3], cmulc(v[11], w3));
    v[4] = padd(v[4], cmulc(v[12], mi(w)));
    v[5] = padd(v[5], cmulc(v[13], mi(w1)));
    v[6] = padd(v[6], cmulc(v[14], mi(w2)));
    v[7] = padd(v[7], cmulc(v[15], mi(w3)));
}

// Forward stages 12,13 on a contiguous 4-block: dist 2 (tw {1,-i}) then dist 1 (tw 1).
__device__ __forceinline__ void dif2(float2 v[4]) {
    { float2 s = padd(v[0], v[2]); float2 d = psub(v[0], v[2]); v[0] = s; v[2] = d; }
    { float2 s = padd(v[1], v[3]); float2 d = psub(v[1], v[3]); v[1] = s; v[3] = mi(d); }
    { float2 s = padd(v[0], v[1]); float2 d = psub(v[0], v[1]); v[0] = s; v[1] = d; }
    { float2 s = padd(v[2], v[3]); float2 d = psub(v[2], v[3]); v[2] = s; v[3] = d; }
}
// Inverse stages 0,1 on a contiguous 4-block: dist 1 (tw 1) then dist 2 (tw {1,+i}).
__device__ __forceinline__ void dit2(float2 v[4]) {
    { float2 s = padd(v[0], v[1]); float2 d = psub(v[0], v[1]); v[0] = s; v[1] = d; }
    { float2 s = padd(v[2], v[3]); float2 d = psub(v[2], v[3]); v[2] = s; v[3] = d; }
    { float2 s = padd(v[0], v[2]); float2 d = psub(v[0], v[2]); v[0] = s; v[2] = d; }
    { float2 t = make_float2(-v[3].y, v[3].x);             // v3 * (+i)
      float2 s = padd(v[1], t); float2 d = psub(v[1], t);
      v[1] = s; v[3] = d; }
}
// Pointwise pair: za = Z[k], zb = Z[N-k]  ->  za = Y(k), zb = conj(Y(k)).
__device__ __forceinline__ void pw(float2& za, float2& zb, float s4) {
    float2 z2c = make_float2(zb.x, -zb.y);
    float2 X2  = padd(za, z2c);
    float2 G   = psub(z2c, za);
    float2 F2  = make_float2(-G.y, G.x);                    // i * G
    float2 Y   = cmul(X2, F2);
    Y.x *= s4; Y.y *= s4;
    za = Y; zb = make_float2(Y.x, -Y.y);
}
// Self-paired bin (k == N-k): Y = Re(z)*Im(z)*scale, purely real.
__device__ __forceinline__ void pws(float2& z, float s4) {
    z = make_float2(z.x * z.y * (4.0f * s4), 0.0f);
}

extern "C" __global__ void __launch_bounds__(NT, 1)
fftconv_kernel(const float* __restrict__ x, const float* __restrict__ f,
               const int* __restrict__ pos32, float* __restrict__ out) {
    // smem: [0,1024) float2 twiddles; [1024,1024+NFFT) float2 working set;
    //       then 2*LSEQ floats input staging (cp.async prefetch target). 200 KB.
    extern __shared__ float2 smem_all[];
    float2* s_tw = smem_all;
    float2* sm   = smem_all + 1024;
    float*  s_x  = (float*)(smem_all + 1024 + NFFT);
    float*  s_f  = s_x + LSEQ;

    const int t = threadIdx.x;

    // Per-CTA twiddle: W^t = exp(-2*pi*i*t/16384) (published by first barrier).
    float2 w_t;
    __sincosf((float)t * (-6.283185307179586477f / 16384.0f), &w_t.y, &w_t.x);
    s_tw[t] = w_t;

    // positions dtype: int64 vs int32 (hoisted; uniform across rows).
    bool is64 = true;
    #pragma unroll
    for (int i = 0; i < 8; i++) {
        int hi = __ldg(pos32 + 2 * i + 1);
        if (hi != 0 && hi != -1) is64 = false;
    }

    const int swt  = sw(t);        // sw(t + 1024j) == sw(t) + 1024j
    const int nbar = 1 + (t >> 7); // named barrier ids 1..8 (0 = __syncthreads)
    const int stride = gridDim.x;
    const float s4 = 0.25f / ((float)NFFT * (float)NFFT);

    bool from_stage = false;       // v comes from s_x/s_f (prefetched)?

    for (int row = blockIdx.x; row < NROWS; row += stride) {
        const int b = row / DCH;
        float2 v[16];

        // ---- Obtain input row (global on first iter, staged afterwards) ----
        if (from_stage) {
            asm volatile("cp.async.wait_group 0;" ::: "memory");
            __syncthreads();
            #pragma unroll
            for (int j = 0; j < 8; j++)
                v[j] = make_float2(s_x[t + 1024 * j], s_f[t + 1024 * j]);
        } else {
            const float* xr = x + (size_t)row * LSEQ;
            const float* fr = f + (size_t)row * LSEQ;
            #pragma unroll
            for (int j = 0; j < 8; j++) {
                int e = t + 1024 * j;
                v[j] = make_float2(xr[e], fr[e]);
            }
        }

        // ---- Mask bits for this row (latency overlaps forward FFT) ----
        unsigned mbits = 0;
        if (is64) {
            const long long* p = (const long long*)pos32 + (size_t)b * LSEQ;
            #pragma unroll
            for (int j = 0; j < 8; j++)
                mbits |= (__ldg(p + t + 1024 * j) != -1LL ? 1u : 0u) << j;
        } else {
            const int* p = pos32 + (size_t)b * LSEQ;
            #pragma unroll
            for (int j = 0; j < 8; j++)
                mbits |= (__ldg(p + t + 1024 * j) != -1 ? 1u : 0u) << j;
        }

        // ---- Forward FFT (DIF, natural -> bit-reversed) ----
        dif4_zero(v, w_t);                                 // stages 0-3, stride 1024
        #pragma unroll
        for (int j = 0; j < 16; j++) sm[swt + 1024 * j] = v[j];
        __syncthreads();   // publishes s_tw (iter 0); separates staging consume/refill

        // ---- Prefetch next row into staging (background LDGSTS) ----
        {
            int nrow = row + stride;
            if (nrow < NROWS) {
                const float* xn = x + (size_t)nrow * LSEQ;
                const float* fn = f + (size_t)nrow * LSEQ;
                #pragma unroll
                for (int p = 0; p < 2; p++) {
                    int o = 4 * t + 4096 * p;
                    cp16(s_x + o, xn + o);
                    cp16(s_f + o, fn + o);
                }
                asm volatile("cp.async.commit_group;" ::: "memory");
                from_stage = true;
            } else {
                from_stage = false;
            }
        }

        {
            // stride-64 round: sw(base + 64j) == (e1 ^ ((j&3)<<2)) + 64j
            int g = t >> 6, r = t & 63, base = g * 1024 + r;
            int e1 = base ^ ((r >> 4) & 3);
            #pragma unroll
            for (int j = 0; j < 16; j++) v[j] = sm[(e1 ^ ((j & 3) << 2)) + 64 * j];
            dif4(v, s_tw[r << 4]);                         // stages 4-7
            #pragma unroll
            for (int j = 0; j < 16; j++) sm[(e1 ^ ((j & 3) << 2)) + 64 * j] = v[j];
        }
        asm volatile("bar.sync %0, 128;" :: "r"(nbar) : "memory");
        {
            // stride-4 round: sw(h*64 + q + 4j) == h*64 + (q^d) + 16d + ((4*jl)^h4)
            int h = t >> 2, q = t & 3;
            int hb = h * 64;
            int h4 = (h & 3) << 2;
            #pragma unroll
            for (int j = 0; j < 16; j++) {
                int d = j >> 2, jl = j & 3;
                v[j] = sm[hb + (q ^ d) + 16 * d + ((4 * jl) ^ h4)];
            }
            dif4(v, s_tw[q << 8]);                         // stages 8-11
            #pragma unroll
            for (int j = 0; j < 16; j++) {
                int d = j >> 2, jl = j & 3;
                sm[hb + (q ^ d) + 16 * d + ((4 * jl) ^ h4)] = v[j];
            }
        }
        __syncthreads();

        // ---- FUSED: fwd stages 12-13 + pointwise + inv stages 0-1 ----
        {
            int w = t >> 5, l = t & 31;
            #pragma unroll
            for (int m = 0; m < 2; m++) {
                int u = ((2 * w + m) << 5) | l;
                float2 a[4], c[4];
                if (u == 0) {
                    #pragma unroll
                    for (int j = 0; j < 4; j++) { a[j] = sm[sw(j)]; c[j] = sm[sw(4 + j)]; }
                    dif2(a); dif2(c);
                    pws(a[0], s4);          // k = 0
                    pws(a[1], s4);          // k = 8192
                    pw(a[2], a[3], s4);     // 4096 <-> 12288
                    pw(c[0], c[3], s4);     // 2048 <-> 14336
                    pw(c[1], c[2], s4);     // 10240 <-> 6144
                    dit2(a); dit2(c);
                    #pragma unroll
                    for (int j = 0; j < 4; j++) { sm[sw(j)] = a[j]; sm[sw(4 + j)] = c[j]; }
                } else {
                    int BA = 2 * u;
                    int k0 = __brev(BA) >> 20;                 // brev12
                    int BB = __brev(4096 - k0) >> 20;          // partner (odd) block
                    #pragma unroll
                    for (int j = 0; j < 4; j++) {
                        a[j] = sm[sw(4 * BA + j)];
                        c[j] = sm[sw(4 * BB + j)];
                    }
                    dif2(a); dif2(c);
                    pw(a[0], c[3], s4);
                    pw(a[1], c[2], s4);
                    pw(a[2], c[1], s4);
                    pw(a[3], c[0], s4);
                    dit2(a); dit2(c);
                    #pragma unroll
                    for (int j = 0; j < 4; j++) {
                        sm[sw(4 * BA + j)] = a[j];
                        sm[sw(4 * BB + j)] = c[j];
                    }
                }
            }
        }
        __syncthreads();

        // ---- Inverse FFT (DIT, bit-reversed -> natural, unnormalized) ----
        {
            int h = t >> 2, q = t & 3;
            int hb = h * 64;
            int h4 = (h & 3) << 2;
            #pragma unroll
            for (int j = 0; j < 16; j++) {
                int d = j >> 2, jl = j & 3;
                v[j] = sm[hb + (q ^ d) + 16 * d + ((4 * jl) ^ h4)];
            }
            dit4(v, s_tw[q << 8]);                         // stages 2-5
            #pragma unroll
            for (int j = 0; j < 16; j++) {
                int d = j >> 2, jl = j & 3;
                sm[hb + (q ^ d) + 16 * d + ((4 * jl) ^ h4)] = v[j];
            }
        }
        asm volatile("bar.sync %0, 128;" :: "r"(nbar) : "memory");
        {
            int g = t >> 6, r = t & 63, base = g * 1024 + r;
            int e1 = base ^ ((r >> 4) & 3);
            #pragma unroll
            for (int j = 0; j < 16; j++) v[j] = sm[(e1 ^ ((j & 3) << 2)) + 64 * j];
            dit4(v, s_tw[r << 4]);                         // stages 6-9
            #pragma unroll
            for (int j = 0; j < 16; j++) sm[(e1 ^ ((j & 3) << 2)) + 64 * j] = v[j];
        }
        __syncthreads();
        {
            #pragma unroll
            for (int j = 0; j < 16; j++) v[j] = sm[swt + 1024 * j];
            dit4_half(v, w_t);                             // stages 10-13 ("+" half)

            float* orow = out + (size_t)row * LSEQ;
            #pragma unroll
            for (int j = 0; j < 8; j++) {
                int l = t + 1024 * j;
                orow[l] = (mbits >> j & 1u) ? v[j].x : 0.0f;
            }
        }
        __syncthreads();   // sm reuse safety before next iteration's round 1 stores
    }
}

extern "C" void kernel_launch(void* const* d_in, const int* in_sizes, int n_in,
                              void* d_out, int out_size) {
    const float* x   = (const float*)d_in[0];
    const float* f   = (const float*)d_in[1];
    const int*   pos = (const int*)d_in[2];
    float*       out = (float*)d_out;

    int dev = 0, nsm = 148;
    cudaGetDevice(&dev);
    cudaDeviceGetAttribute(&nsm, cudaDevAttrMultiProcessorCount, dev);
    if (nsm < 1 || nsm > NROWS) nsm = 148;

    const int smem_bytes = (1024 + NFFT) * sizeof(float2) + 2 * LSEQ * sizeof(float);
    cudaFuncSetAttribute(fftconv_kernel,
                         cudaFuncAttributeMaxDynamicSharedMemorySize,
                         smem_bytes);

    fftconv_kernel<<<nsm, NT, smem_bytes>>>(x, f, pos, out);
}

// round 16
// speedup vs baseline: 1.0714x; 1.0714x over previous
#include <cuda_runtime.h>

#define NFFT   16384
#define LOGN   14
#define LSEQ   8192
#define NT     1024
#define DCH    256
#define NROWS  2048

typedef unsigned long long u64;

// ---- packed f32x2 add/sub (sm_103a; ptxas never emits these from C++) ----
__device__ __forceinline__ float2 padd(float2 a, float2 b) {
    float2 r;
    asm("add.rn.f32x2 %0, %1, %2;"
        : "=l"(reinterpret_cast<u64&>(r))
        : "l"(reinterpret_cast<u64&>(a)), "l"(reinterpret_cast<u64&>(b)));
    return r;
}
__device__ __forceinline__ float2 psub(float2 a, float2 b) {
    float2 r;
    asm("sub.rn.f32x2 %0, %1, %2;"
        : "=l"(reinterpret_cast<u64&>(r))
        : "l"(reinterpret_cast<u64&>(a)), "l"(reinterpret_cast<u64&>(b)));
    return r;
}

// scalar complex multiply (round-10 showed packed fma here is a LOSS)
__device__ __forceinline__ float2 cmul(float2 a, float2 b) {
    return make_float2(fmaf(a.x, b.x, -a.y * b.y), fmaf(a.x, b.y, a.y * b.x));
}
// a * conj(b)
__device__ __forceinline__ float2 cmulc(float2 a, float2 b) {
    return make_float2(fmaf(a.x, b.x,  a.y * b.y), fmaf(a.y, b.x, -a.x * b.y));
}
__device__ __forceinline__ float2 mi(float2 z) { return make_float2(z.y, -z.x); }  // z * (-i)
__device__ __forceinline__ int sw(int i) { return i ^ ((i >> 4) & 15); }

#define C16_1 make_float2(0.923879532511286756f, -0.382683432365089772f)
#define C16_2 make_float2(0.707106781186547524f, -0.707106781186547524f)
#define C16_3 make_float2(0.382683432365089772f, -0.923879532511286756f)

// DIF butterfly: a' = a+b ; b' = (a-b)*tw
__device__ __forceinline__ void bf(float2& a, float2& b, float2 tw) {
    float2 s = padd(a, b);
    float2 d = psub(a, b);
    a = s; b = cmul(d, tw);
}
// DIT butterfly: t = b*conj(tw) ; a' = a+t ; b' = a-t
__device__ __forceinline__ void bfi(float2& a, float2& b, float2 tw) {
    float2 t = cmulc(b, tw);
    float2 s = padd(a, t);
    b = psub(a, t);
    a = s;
}

// Forward stages at local distances 4, 2, 1 (shared tail of a radix-16 group).
__device__ __forceinline__ void dif_stages123(float2 v[16], float2 ws2) {
    float2 u = cmul(ws2, C16_2);
    bf(v[0], v[4],  ws2); bf(v[1], v[5],  u); bf(v[2],  v[6],  mi(ws2)); bf(v[3],  v[7],  mi(u));
    bf(v[8], v[12], ws2); bf(v[9], v[13], u); bf(v[10], v[14], mi(ws2)); bf(v[11], v[15], mi(u));
    float2 ws4 = cmul(ws2, ws2);
    #pragma unroll
    for (int b = 0; b < 4; b++) {
        bf(v[4*b],   v[4*b+2], ws4);
        bf(v[4*b+1], v[4*b+3], mi(ws4));
    }
    float2 ws8 = cmul(ws4, ws4);
    #pragma unroll
    for (int b = 0; b < 8; b++) bf(v[2*b], v[2*b+1], ws8);
}

// Full 4-stage forward group, base twiddle w (distances 8,4,2,1).
__device__ __forceinline__ void dif4(float2 v[16], float2 w) {
    float2 w1 = cmul(w, C16_1), w2 = cmul(w, C16_2), w3 = cmul(w, C16_3);
    bf(v[0], v[8],  w);     bf(v[1], v[9],  w1);     bf(v[2], v[10], w2);     bf(v[3], v[11], w3);
    bf(v[4], v[12], mi(w)); bf(v[5], v[13], mi(w1)); bf(v[6], v[14], mi(w2)); bf(v[7], v[15], mi(w3));
    dif_stages123(v, cmul(w, w));
}

// First forward group with v[8..15] == 0 (zero-padding): stage 0 degenerates.
__device__ __forceinline__ void dif4_zero(float2 v[16], float2 w) {
    float2 w1 = cmul(w, C16_1), w2 = cmul(w, C16_2), w3 = cmul(w, C16_3);
    v[8]  = cmul(v[0], w);      v[9]  = cmul(v[1], w1);
    v[10] = cmul(v[2], w2);     v[11] = cmul(v[3], w3);
    v[12] = cmul(v[4], mi(w));  v[13] = cmul(v[5], mi(w1));
    v[14] = cmul(v[6], mi(w2)); v[15] = cmul(v[7], mi(w3));
    dif_stages123(v, cmul(w, w));
}

// Full 4-stage inverse group, base twiddle w (distances 1,2,4,8), conj twiddles.
__device__ __forceinline__ void dit4(float2 v[16], float2 w) {
    float2 ws2 = cmul(w, w), ws4 = cmul(ws2, ws2), ws8 = cmul(ws4, ws4);
    #pragma unroll
    for (int b = 0; b < 8; b++) bfi(v[2*b], v[2*b+1], ws8);
    #pragma unroll
    for (int b = 0; b < 4; b++) {
        bfi(v[4*b],   v[4*b+2], ws4);
        bfi(v[4*b+1], v[4*b+3], mi(ws4));
    }
    float2 u = cmul(ws2, C16_2);
    bfi(v[0], v[4],  ws2); bfi(v[1], v[5],  u); bfi(v[2],  v[6],  mi(ws2)); bfi(v[3],  v[7],  mi(u));
    bfi(v[8], v[12], ws2); bfi(v[9], v[13], u); bfi(v[10], v[14], mi(ws2)); bfi(v[11], v[15], mi(u));
    float2 w1 = cmul(w, C16_1), w2 = cmul(w, C16_2), w3 = cmul(w, C16_3);
    bfi(v[0], v[8],  w);     bfi(v[1], v[9],  w1);     bfi(v[2], v[10], w2);     bfi(v[3], v[11], w3);
    bfi(v[4], v[12], mi(w)); bfi(v[5], v[13], mi(w1)); bfi(v[6], v[14], mi(w2)); bfi(v[7], v[15], mi(w3));
}

// Same but last stage (dist 8) emits ONLY the "+" half v[0..7] — the "-"
// outputs map to positions >= 8192 which are discarded.
__device__ __forceinline__ void dit4_half(float2 v[16], float2 w) {
    float2 ws2 = cmul(w, w), ws4 = cmul(ws2, ws2), ws8 = cmul(ws4, ws4);
    #pragma unroll
    for (int b = 0; b < 8; b++) bfi(v[2*b], v[2*b+1], ws8);
    #pragma unroll
    for (int b = 0; b < 4; b++) {
        bfi(v[4*b],   v[4*b+2], ws4);
        bfi(v[4*b+1], v[4*b+3], mi(ws4));
    }
    float2 u = cmul(ws2, C16_2);
    bfi(v[0], v[4],  ws2); bfi(v[1], v[5],  u); bfi(v[2],  v[6],  mi(ws2)); bfi(v[3],  v[7],  mi(u));
    bfi(v[8], v[12], ws2); bfi(v[9], v[13], u); bfi(v[10], v[14], mi(ws2)); bfi(v[11], v[15], mi(u));
    float2 w1 = cmul(w, C16_1), w2 = cmul(w, C16_2), w3 = cmul(w, C16_3);
    v[0] = padd(v[0], cmulc(v[8],  w));
    v[1] = padd(v[1], cmulc(v[9],  w1));
    v[2] = padd(v[2], cmulc(v[10], w2));
    v[3] = padd(v[3], cmulc(v[11], w3));
    v[4] = padd(v[4], cmulc(v[12], mi(w)));
    v[5] = padd(v[5], cmulc(v[13], mi(w1)));
    v[6] = padd(v[6], cmulc(v[14], mi(w2)));
    v[7] = padd(v[7], cmulc(v[15], mi(w3)));
}

// Forward stages 12,13 on a contiguous 4-block: dist 2 (tw {1,-i}) then dist 1 (tw 1).
__device__ __forceinline__ void dif2(float2* v) {
    { float2 s = padd(v[0], v[2]); float2 d = psub(v[0], v[2]); v[0] = s; v[2] = d; }
    { float2 s = padd(v[1], v[3]); float2 d = psub(v[1], v[3]); v[1] = s; v[3] = mi(d); }
    { float2 s = padd(v[0], v[1]); float2 d = psub(v[0], v[1]); v[0] = s; v[1] = d; }
    { float2 s = padd(v[2], v[3]); float2 d = psub(v[2], v[3]); v[2] = s; v[3] = d; }
}
// Inverse stages 0,1 on a contiguous 4-block: dist 1 (tw 1) then dist 2 (tw {1,+i}).
__device__ __forceinline__ void dit2(float2* v) {
    { float2 s = padd(v[0], v[1]); float2 d = psub(v[0], v[1]); v[0] = s; v[1] = d; }
    { float2 s = padd(v[2], v[3]); float2 d = psub(v[2], v[3]); v[2] = s; v[3] = d; }
    { float2 s = padd(v[0], v[2]); float2 d = psub(v[0], v[2]); v[0] = s; v[2] = d; }
    { float2 t = make_float2(-v[3].y, v[3].x);             // v3 * (+i)
      float2 s = padd(v[1], t); float2 d = psub(v[1], t);
      v[1] = s; v[3] = d; }
}
// Pointwise pair: za = Z[k], zb = Z[N-k]  ->  za = Y(k), zb = conj(Y(k)).
__device__ __forceinline__ void pw(float2& za, float2& zb, float s4) {
    float2 z2c = make_float2(zb.x, -zb.y);
    float2 X2  = padd(za, z2c);
    float2 G   = psub(z2c, za);
    float2 F2  = make_float2(-G.y, G.x);                    // i * G
    float2 Y   = cmul(X2, F2);
    Y.x *= s4; Y.y *= s4;
    za = Y; zb = make_float2(Y.x, -Y.y);
}
// Self-paired bin (k == N-k): Y = Re(z)*Im(z)*scale, purely real.
__device__ __forceinline__ void pws(float2& z, float s4) {
    z = make_float2(z.x * z.y * (4.0f * s4), 0.0f);
}

extern "C" __global__ void __launch_bounds__(NT, 1)
fftconv_kernel(const float* __restrict__ x, const float* __restrict__ f,
               const int* __restrict__ pos32, float* __restrict__ out) {
    // smem: [0, 1024) twiddle table W^k (k < 1024 — all the FFT ever reads);
    //       [1024, 1024+NFFT) FFT working set.
    extern __shared__ float2 smem_all[];
    float2* s_tw = smem_all;
    float2* sm   = smem_all + 1024;

    const int row = blockIdx.x;
    const int b   = row / DCH;
    const int t   = threadIdx.x;
    const float* __restrict__ xr = x + (size_t)row * LSEQ;
    const float* __restrict__ fr = f + (size_t)row * LSEQ;

    float2 v[16];

    // ---- Load (pattern e = t + 1024j), pack z = x + i*f; upper half zero ----
    #pragma unroll
    for (int j = 0; j < 8; j++) {
        int e = t + 1024 * j;
        v[j] = make_float2(xr[e], fr[e]);
    }

    // ---- Per-CTA twiddle: W^t = exp(-2*pi*i*t/16384), t < 1024 ----
    float2 w_t;
    __sincosf((float)t * (-6.283185307179586477f / 16384.0f), &w_t.y, &w_t.x);
    s_tw[t] = w_t;

    // ---- Mask from positions (int64 vs int32 via high-word probes);
    //      latency overlaps the forward FFT compute. ----
    unsigned mbits = 0;
    {
        bool is64 = true;
        #pragma unroll
        for (int i = 0; i < 8; i++) {
            int hi = __ldg(pos32 + 2 * i + 1);
            if (hi != 0 && hi != -1) is64 = false;
        }
        if (is64) {
            const long long* p = (const long long*)pos32 + (size_t)b * LSEQ;
            #pragma unroll
            for (int j = 0; j < 8; j++)
                mbits |= (__ldg(p + t + 1024 * j) != -1LL ? 1u : 0u) << j;
        } else {
            const int* p = pos32 + (size_t)b * LSEQ;
            #pragma unroll
            for (int j = 0; j < 8; j++)
                mbits |= (__ldg(p + t + 1024 * j) != -1 ? 1u : 0u) << j;
        }
    }

    const int swt  = sw(t);       // sw(t + 1024j) == sw(t) + 1024j
    // Named barrier ids 1..8 (id 0 is the __syncthreads barrier).
    const int nbar = 1 + (t >> 7);

    // ---- Forward FFT (DIF, natural -> bit-reversed) ----
    dif4_zero(v, w_t);                                 // stages 0-3, stride 1024
    #pragma unroll
    for (int j = 0; j < 16; j++) sm[swt + 1024 * j] = v[j];
    __syncthreads();                                   // also publishes s_tw
    {
        // stride-64 round: sw(base + 64j) == (e1 ^ ((j&3)<<2)) + 64j
        int g = t >> 6, r = t & 63, base = g * 1024 + r;
        int e1 = base ^ ((r >> 4) & 3);
        #pragma unroll
        for (int j = 0; j < 16; j++) v[j] = sm[(e1 ^ ((j & 3) << 2)) + 64 * j];
        dif4(v, s_tw[r << 4]);                         // stages 4-7
        #pragma unroll
        for (int j = 0; j < 16; j++) sm[(e1 ^ ((j & 3) << 2)) + 64 * j] = v[j];
    }
    // R2 -> R3 exchange confined to this group's two 1024-blocks.
    asm volatile("bar.sync %0, 128;" :: "r"(nbar) : "memory");
    {
        // stride-4 round: sw(h*64 + q + 4j) == h*64 + (q^d) + 16d + ((4*jl)^h4)
        int h = t >> 2, q = t & 3;
        int hb = h * 64;
        int h4 = (h & 3) << 2;
        #pragma unroll
        for (int j = 0; j < 16; j++) {
            int d = j >> 2, jl = j & 3;
            v[j] = sm[hb + (q ^ d) + 16 * d + ((4 * jl) ^ h4)];
        }
        dif4(v, s_tw[q << 8]);                         // stages 8-11
        #pragma unroll
        for (int j = 0; j < 16; j++) {
            int d = j >> 2, jl = j & 3;
            sm[hb + (q ^ d) + 16 * d + ((4 * jl) ^ h4)] = v[j];
        }
    }
    __syncthreads();

    // ---- FUSED: fwd stages 12-13 + pointwise + inv stages 0-1, all in regs.
    //      Both units' loads batched up front (2x MLP on the scattered round).
    //      Block pairing is a perfect matching (BA even <-> BB odd), so the
    //      two units touch disjoint blocks; stores return to read addresses. ----
    const float s4 = 0.25f / ((float)NFFT * (float)NFFT);
    {
        int wg = t >> 5, l = t & 31;
        int u0 = ((2 * wg + 0) << 5) | l;
        int u1 = ((2 * wg + 1) << 5) | l;
        int k0s[2], BBs[2];
        // unit 0
        if (u0 == 0) { k0s[0] = 0; BBs[0] = 1; }
        else {
            k0s[0] = __brev(2 * u0) >> 20;
            BBs[0] = __brev(4096 - k0s[0]) >> 20;
        }
        // unit 1 (u1 >= 32, never the special case)
        k0s[1] = __brev(2 * u1) >> 20;
        BBs[1] = __brev(4096 - k0s[1]) >> 20;

        // batched loads: v[0..3]=a0, v[4..7]=c0, v[8..11]=a1, v[12..15]=c1
        #pragma unroll
        for (int j = 0; j < 4; j++) {
            v[j]      = sm[sw(8 * u0 + j)];
            v[4 + j]  = sm[sw(4 * BBs[0] + j)];
            v[8 + j]  = sm[sw(8 * u1 + j)];
            v[12 + j] = sm[sw(4 * BBs[1] + j)];
        }

        #pragma unroll
        for (int m = 0; m < 2; m++) {
            float2* a = v + 8 * m;
            float2* c = v + 8 * m + 4;
            dif2(a); dif2(c);
            if (m == 0 && u0 == 0) {
                pws(a[0], s4);          // k = 0
                pws(a[1], s4);          // k = 8192
                pw(a[2], a[3], s4);     // 4096 <-> 12288
                pw(c[0], c[3], s4);     // 2048 <-> 14336
                pw(c[1], c[2], s4);     // 10240 <-> 6144
            } else {
                pw(a[0], c[3], s4);
                pw(a[1], c[2], s4);
                pw(a[2], c[1], s4);
                pw(a[3], c[0], s4);
            }
            dit2(a); dit2(c);
        }

        #pragma unroll
        for (int j = 0; j < 4; j++) {
            sm[sw(8 * u0 + j)]        = v[j];
            sm[sw(4 * BBs[0] + j)]    = v[4 + j];
            sm[sw(8 * u1 + j)]        = v[8 + j];
            sm[sw(4 * BBs[1] + j)]    = v[12 + j];
        }
    }
    __syncthreads();

    // ---- Inverse FFT (DIT, bit-reversed -> natural, unnormalized) ----
    {
        int h = t >> 2, q = t & 3;
        int hb = h * 64;
        int h4 = (h & 3) << 2;
        #pragma unroll
        for (int j = 0; j < 16; j++) {
            int d = j >> 2, jl = j & 3;
            v[j] = sm[hb + (q ^ d) + 16 * d + ((4 * jl) ^ h4)];
        }
        dit4(v, s_tw[q << 8]);                         // stages 2-5
        #pragma unroll
        for (int j = 0; j < 16; j++) {
            int d = j >> 2, jl = j & 3;
            sm[hb + (q ^ d) + 16 * d + ((4 * jl) ^ h4)] = v[j];
        }
    }
    // R5 -> R6 exchange confined to this group's two 1024-blocks.
    asm volatile("bar.sync %0, 128;" :: "r"(nbar) : "memory");
    {
        int g = t >> 6, r = t & 63, base = g * 1024 + r;
        int e1 = base ^ ((r >> 4) & 3);
        #pragma unroll
        for (int j = 0; j < 16; j++) v[j] = sm[(e1 ^ ((j & 3) << 2)) + 64 * j];
        dit4(v, s_tw[r << 4]);                         // stages 6-9
        #pragma unroll
        for (int j = 0; j < 16; j++) sm[(e1 ^ ((j & 3) << 2)) + 64 * j] = v[j];
    }
    __syncthreads();
    {
        #pragma unroll
        for (int j = 0; j < 16; j++) v[j] = sm[swt + 1024 * j];
        dit4_half(v, w_t);                             // stages 10-13 ("+" half only)

        // ---- Store first LSEQ real samples, masked by pre-fetched bits ----
        #pragma unroll
        for (int j = 0; j < 8; j++) {
            int l = t + 1024 * j;
            out[(size_t)row * LSEQ + l] = (mbits >> j & 1u) ? v[j].x : 0.0f;
        }
    }
}

extern "C" void kernel_launch(void* const* d_in, const int* in_sizes, int n_in,
                              void* d_out, int out_size) {
    const float* x   = (const float*)d_in[0];
    const float* f   = (const float*)d_in[1];
    const int*   pos = (const int*)d_in[2];
    float*       out = (float*)d_out;

    const int smem_bytes = (NFFT + 1024) * sizeof(float2);   // 136 KB
    cudaFuncSetAttribute(fftconv_kernel,
                         cudaFuncAttributeMaxDynamicSharedMemorySize,
                         smem_bytes);

    fftconv_kernel<<<NROWS, NT, smem_bytes>>>(x, f, pos, out);
}

// round 17
// speedup vs baseline: 1.1098x; 1.0358x over previous
#include <cuda_runtime.h>

#define NFFT   16384
#define LOGN   14
#define LSEQ   8192
#define NT     1024
#define DCH    256
#define NROWS  2048

typedef unsigned long long u64;

// ---- packed f32x2 add/sub (sm_103a; ptxas never emits these from C++) ----
__device__ __forceinline__ float2 padd(float2 a, float2 b) {
    float2 r;
    asm("add.rn.f32x2 %0, %1, %2;"
        : "=l"(reinterpret_cast<u64&>(r))
        : "l"(reinterpret_cast<u64&>(a)), "l"(reinterpret_cast<u64&>(b)));
    return r;
}
__device__ __forceinline__ float2 psub(float2 a, float2 b) {
    float2 r;
    asm("sub.rn.f32x2 %0, %1, %2;"
        : "=l"(reinterpret_cast<u64&>(r))
        : "l"(reinterpret_cast<u64&>(a)), "l"(reinterpret_cast<u64&>(b)));
    return r;
}

// scalar complex multiply (round-10 showed packed fma here is a LOSS)
__device__ __forceinline__ float2 cmul(float2 a, float2 b) {
    return make_float2(fmaf(a.x, b.x, -a.y * b.y), fmaf(a.x, b.y, a.y * b.x));
}
// a * conj(b)
__device__ __forceinline__ float2 cmulc(float2 a, float2 b) {
    return make_float2(fmaf(a.x, b.x,  a.y * b.y), fmaf(a.y, b.x, -a.x * b.y));
}
__device__ __forceinline__ float2 mi(float2 z) { return make_float2(z.y, -z.x); }  // z * (-i)
__device__ __forceinline__ int sw(int i) { return i ^ ((i >> 4) & 15); }

#define C16_1 make_float2(0.923879532511286756f, -0.382683432365089772f)
#define C16_2 make_float2(0.707106781186547524f, -0.707106781186547524f)
#define C16_3 make_float2(0.382683432365089772f, -0.923879532511286756f)

// DIF butterfly: a' = a+b ; b' = (a-b)*tw
__device__ __forceinline__ void bf(float2& a, float2& b, float2 tw) {
    float2 s = padd(a, b);
    float2 d = psub(a, b);
    a = s; b = cmul(d, tw);
}
// DIT butterfly: t = b*conj(tw) ; a' = a+t ; b' = a-t
__device__ __forceinline__ void bfi(float2& a, float2& b, float2 tw) {
    float2 t = cmulc(b, tw);
    float2 s = padd(a, t);
    b = psub(a, t);
    a = s;
}

// Forward stages at local distances 4, 2, 1 (shared tail of a radix-16 group).
__device__ __forceinline__ void dif_stages123(float2 v[16], float2 ws2) {
    float2 u = cmul(ws2, C16_2);
    bf(v[0], v[4],  ws2); bf(v[1], v[5],  u); bf(v[2],  v[6],  mi(ws2)); bf(v[3],  v[7],  mi(u));
    bf(v[8], v[12], ws2); bf(v[9], v[13], u); bf(v[10], v[14], mi(ws2)); bf(v[11], v[15], mi(u));
    float2 ws4 = cmul(ws2, ws2);
    #pragma unroll
    for (int b = 0; b < 4; b++) {
        bf(v[4*b],   v[4*b+2], ws4);
        bf(v[4*b+1], v[4*b+3], mi(ws4));
    }
    float2 ws8 = cmul(ws4, ws4);
    #pragma unroll
    for (int b = 0; b < 8; b++) bf(v[2*b], v[2*b+1], ws8);
}

// Full 4-stage forward group, base twiddle w (distances 8,4,2,1).
__device__ __forceinline__ void dif4(float2 v[16], float2 w) {
    float2 w1 = cmul(w, C16_1), w2 = cmul(w, C16_2), w3 = cmul(w, C16_3);
    bf(v[0], v[8],  w);     bf(v[1], v[9],  w1);     bf(v[2], v[10], w2);     bf(v[3], v[11], w3);
    bf(v[4], v[12], mi(w)); bf(v[5], v[13], mi(w1)); bf(v[6], v[14], mi(w2)); bf(v[7], v[15], mi(w3));
    dif_stages123(v, cmul(w, w));
}

// First forward group with v[8..15] == 0 (zero-padding): stage 0 degenerates.
__device__ __forceinline__ void dif4_zero(float2 v[16], float2 w) {
    float2 w1 = cmul(w, C16_1), w2 = cmul(w, C16_2), w3 = cmul(w, C16_3);
    v[8]  = cmul(v[0], w);      v[9]  = cmul(v[1], w1);
    v[10] = cmul(v[2], w2);     v[11] = cmul(v[3], w3);
    v[12] = cmul(v[4], mi(w));  v[13] = cmul(v[5], mi(w1));
    v[14] = cmul(v[6], mi(w2)); v[15] = cmul(v[7], mi(w3));
    dif_stages123(v, cmul(w, w));
}

// Full 4-stage inverse group, base twiddle w (distances 1,2,4,8), conj twiddles.
__device__ __forceinline__ void dit4(float2 v[16], float2 w) {
    float2 ws2 = cmul(w, w), ws4 = cmul(ws2, ws2), ws8 = cmul(ws4, ws4);
    #pragma unroll
    for (int b = 0; b < 8; b++) bfi(v[2*b], v[2*b+1], ws8);
    #pragma unroll
    for (int b = 0; b < 4; b++) {
        bfi(v[4*b],   v[4*b+2], ws4);
        bfi(v[4*b+1], v[4*b+3], mi(ws4));
    }
    float2 u = cmul(ws2, C16_2);
    bfi(v[0], v[4],  ws2); bfi(v[1], v[5],  u); bfi(v[2],  v[6],  mi(ws2)); bfi(v[3],  v[7],  mi(u));
    bfi(v[8], v[12], ws2); bfi(v[9], v[13], u); bfi(v[10], v[14], mi(ws2)); bfi(v[11], v[15], mi(u));
    float2 w1 = cmul(w, C16_1), w2 = cmul(w, C16_2), w3 = cmul(w, C16_3);
    bfi(v[0], v[8],  w);     bfi(v[1], v[9],  w1);     bfi(v[2], v[10], w2);     bfi(v[3], v[11], w3);
    bfi(v[4], v[12], mi(w)); bfi(v[5], v[13], mi(w1)); bfi(v[6], v[14], mi(w2)); bfi(v[7], v[15], mi(w3));
}

// Same but last stage (dist 8) emits ONLY the "+" half v[0..7] — the "-"
// outputs map to positions >= 8192 which are discarded.
__device__ __forceinline__ void dit4_half(float2 v[16], float2 w) {
    float2 ws2 = cmul(w, w), ws4 = cmul(ws2, ws2), ws8 = cmul(ws4, ws4);
    #pragma unroll
    for (int b = 0; b < 8; b++) bfi(v[2*b], v[2*b+1], ws8);
    #pragma unroll
    for (int b = 0; b < 4; b++) {
        bfi(v[4*b],   v[4*b+2], ws4);
        bfi(v[4*b+1], v[4*b+3], mi(ws4));
    }
    float2 u = cmul(ws2, C16_2);
    bfi(v[0], v[4],  ws2); bfi(v[1], v[5],  u); bfi(v[2],  v[6],  mi(ws2)); bfi(v[3],  v[7],  mi(u));
    bfi(v[8], v[12], ws2); bfi(v[9], v[13], u); bfi(v[10], v[14], mi(ws2)); bfi(v[11], v[15], mi(u));
    float2 w1 = cmul(w, C16_1), w2 = cmul(w, C16_2), w3 = cmul(w, C16_3);
    v[0] = padd(v[0], cmulc(v[8],  w));
    v[1] = padd(v[1], cmulc(v[9],  w1));
    v[2] = padd(v[2], cmulc(v[10], w2));
    v[3] = padd(v[3], cmulc(v[11], w3));
    v[4] = padd(v[4], cmulc(v[12], mi(w)));
    v[5] = padd(v[5], cmulc(v[13], mi(w1)));
    v[6] = padd(v[6], cmulc(v[14], mi(w2)));
    v[7] = padd(v[7], cmulc(v[15], mi(w3)));
}

// Forward stages 12,13 on a contiguous 4-block: dist 2 (tw {1,-i}) then dist 1 (tw 1).
__device__ __forceinline__ void dif2(float2* v) {
    { float2 s = padd(v[0], v[2]); float2 d = psub(v[0], v[2]); v[0] = s; v[2] = d; }
    { float2 s = padd(v[1], v[3]); float2 d = psub(v[1], v[3]); v[1] = s; v[3] = mi(d); }
    { float2 s = padd(v[0], v[1]); float2 d = psub(v[0], v[1]); v[0] = s; v[1] = d; }
    { float2 s = padd(v[2], v[3]); float2 d = psub(v[2], v[3]); v[2] = s; v[3] = d; }
}
// Inverse stages 0,1 on a contiguous 4-block: dist 1 (tw 1) then dist 2 (tw {1,+i}).
__device__ __forceinline__ void dit2(float2* v) {
    { float2 s = padd(v[0], v[1]); float2 d = psub(v[0], v[1]); v[0] = s; v[1] = d; }
    { float2 s = padd(v[2], v[3]); float2 d = psub(v[2], v[3]); v[2] = s; v[3] = d; }
    { float2 s = padd(v[0], v[2]); float2 d = psub(v[0], v[2]); v[0] = s; v[2] = d; }
    { float2 t = make_float2(-v[3].y, v[3].x);             // v3 * (+i)
      float2 s = padd(v[1], t); float2 d = psub(v[1], t);
      v[1] = s; v[3] = d; }
}
// Pointwise pair: za = Z[k], zb = Z[N-k]  ->  za = Y(k), zb = conj(Y(k)).
__device__ __forceinline__ void pw(float2& za, float2& zb, float s4) {
    float2 z2c = make_float2(zb.x, -zb.y);
    float2 X2  = padd(za, z2c);
    float2 G   = psub(z2c, za);
    float2 F2  = make_float2(-G.y, G.x);                    // i * G
    float2 Y   = cmul(X2, F2);
    Y.x *= s4; Y.y *= s4;
    za = Y; zb = make_float2(Y.x, -Y.y);
}
// Self-paired bin (k == N-k): Y = Re(z)*Im(z)*scale, purely real.
__device__ __forceinline__ void pws(float2& z, float s4) {
    z = make_float2(z.x * z.y * (4.0f * s4), 0.0f);
}

extern "C" __global__ void __launch_bounds__(NT, 1)
fftconv_kernel(const float* __restrict__ x, const float* __restrict__ f,
               const int* __restrict__ pos32, float* __restrict__ out) {
    // smem: [0, 1024) twiddle table W^k (k < 1024 — all the FFT ever reads);
    //       [1024, 1024+NFFT) FFT working set.
    extern __shared__ float2 smem_all[];
    float2* s_tw = smem_all;
    float2* sm   = smem_all + 1024;

    const int row = blockIdx.x;
    const int b   = row / DCH;
    const int t   = threadIdx.x;
    const float* __restrict__ xr = x + (size_t)row * LSEQ;
    const float* __restrict__ fr = f + (size_t)row * LSEQ;

    float2 v[16];

    // ---- Load (pattern e = t + 1024j), pack z = x + i*f; upper half zero ----
    #pragma unroll
    for (int j = 0; j < 8; j++) {
        int e = t + 1024 * j;
        v[j] = make_float2(xr[e], fr[e]);
    }

    // ---- Per-CTA twiddle: W^t = exp(-2*pi*i*t/16384), t < 1024 ----
    float2 w_t;
    __sincosf((float)t * (-6.283185307179586477f / 16384.0f), &w_t.y, &w_t.x);
    s_tw[t] = w_t;

    // ---- Mask from positions (int64 vs int32 via high-word probes);
    //      latency overlaps the forward FFT compute. ----
    unsigned mbits = 0;
    {
        bool is64 = true;
        #pragma unroll
        for (int i = 0; i < 8; i++) {
            int hi = __ldg(pos32 + 2 * i + 1);
            if (hi != 0 && hi != -1) is64 = false;
        }
        if (is64) {
            const long long* p = (const long long*)pos32 + (size_t)b * LSEQ;
            #pragma unroll
            for (int j = 0; j < 8; j++)
                mbits |= (__ldg(p + t + 1024 * j) != -1LL ? 1u : 0u) << j;
        } else {
            const int* p = pos32 + (size_t)b * LSEQ;
            #pragma unroll
            for (int j = 0; j < 8; j++)
                mbits |= (__ldg(p + t + 1024 * j) != -1 ? 1u : 0u) << j;
        }
    }

    const int swt  = sw(t);       // sw(t + 1024j) == sw(t) + 1024j
    // Named barrier ids 1..8 (id 0 is the __syncthreads barrier).
    const int nbar = 1 + (t >> 7);

    // XOR-fused address bases (all swizzle terms are bit-disjoint -> one LOP3
    // per address):
    //  stride-64 round: addr = e64 ^ K64_j,  K64_j = ((j&3)<<2) ^ (64*j)
    //  stride-4  round: addr = e4  ^ K4_j,   K4_j  = (17*(j>>2)) ^ (4*(j&3))
    const int e64 = ((t >> 6) * 1024 + (t & 63)) ^ ((t >> 4) & 3);
    const int e4  = ((t >> 2) * 64) ^ (t & 3) ^ ((t & 12) /* == ((t>>2)&3)<<2 */);

    // ---- Forward FFT (DIF, natural -> bit-reversed) ----
    dif4_zero(v, w_t);                                 // stages 0-3, stride 1024
    #pragma unroll
    for (int j = 0; j < 16; j++) sm[swt + 1024 * j] = v[j];
    __syncthreads();                                   // also publishes s_tw
    {
        #pragma unroll
        for (int j = 0; j < 16; j++) v[j] = sm[e64 ^ (((j & 3) << 2) ^ (64 * j))];
        dif4(v, s_tw[(t & 63) << 4]);                  // stages 4-7
        #pragma unroll
        for (int j = 0; j < 16; j++) sm[e64 ^ (((j & 3) << 2) ^ (64 * j))] = v[j];
    }
    // R2 -> R3 exchange confined to this group's two 1024-blocks.
    asm volatile("bar.sync %0, 128;" :: "r"(nbar) : "memory");
    {
        #pragma unroll
        for (int j = 0; j < 16; j++)
            v[j] = sm[e4 ^ ((17 * (j >> 2)) ^ (4 * (j & 3)))];
        dif4(v, s_tw[(t & 3) << 8]);                   // stages 8-11
        #pragma unroll
        for (int j = 0; j < 16; j++)
            sm[e4 ^ ((17 * (j >> 2)) ^ (4 * (j & 3)))] = v[j];
    }
    __syncthreads();

    // ---- FUSED: fwd stages 12-13 + pointwise + inv stages 0-1, all in regs ----
    const float s4 = 0.25f / ((float)NFFT * (float)NFFT);
    {
        int wg = t >> 5, l = t & 31;
        #pragma unroll
        for (int m = 0; m < 2; m++) {
            int u = ((2 * wg + m) << 5) | l;
            float2 a[4], c[4];
            if (u == 0) {
                #pragma unroll
                for (int j = 0; j < 4; j++) { a[j] = sm[sw(j)]; c[j] = sm[sw(4 + j)]; }
                dif2(a); dif2(c);
                pws(a[0], s4);          // k = 0
                pws(a[1], s4);          // k = 8192
                pw(a[2], a[3], s4);     // 4096 <-> 12288
                pw(c[0], c[3], s4);     // 2048 <-> 14336
                pw(c[1], c[2], s4);     // 10240 <-> 6144
                dit2(a); dit2(c);
                #pragma unroll
                for (int j = 0; j < 4; j++) { sm[sw(j)] = a[j]; sm[sw(4 + j)] = c[j]; }
            } else {
                int BA = 2 * u;
                int k0 = __brev(BA) >> 20;                 // brev12
                int BB = __brev(4096 - k0) >> 20;          // partner (odd) block
                #pragma unroll
                for (int j = 0; j < 4; j++) {
                    a[j] = sm[sw(4 * BA + j)];
                    c[j] = sm[sw(4 * BB + j)];
                }
                dif2(a); dif2(c);
                pw(a[0], c[3], s4);
                pw(a[1], c[2], s4);
                pw(a[2], c[1], s4);
                pw(a[3], c[0], s4);
                dit2(a); dit2(c);
                #pragma unroll
                for (int j = 0; j < 4; j++) {
                    sm[sw(4 * BA + j)] = a[j];
                    sm[sw(4 * BB + j)] = c[j];
                }
            }
        }
    }
    __syncthreads();

    // ---- Inverse FFT (DIT, bit-reversed -> natural, unnormalized) ----
    {
        #pragma unroll
        for (int j = 0; j < 16; j++)
            v[j] = sm[e4 ^ ((17 * (j >> 2)) ^ (4 * (j & 3)))];
        dit4(v, s_tw[(t & 3) << 8]);                   // stages 2-5
        #pragma unroll
        for (int j = 0; j < 16; j++)
            sm[e4 ^ ((17 * (j >> 2)) ^ (4 * (j & 3)))] = v[j];
    }
    // R5 -> R6 exchange confined to this group's two 1024-blocks.
    asm volatile("bar.sync %0, 128;" :: "r"(nbar) : "memory");
    {
        #pragma unroll
        for (int j = 0; j < 16; j++) v[j] = sm[e64 ^ (((j & 3) << 2) ^ (64 * j))];
        dit4(v, s_tw[(t & 63) << 4]);                  // stages 6-9
        #pragma unroll
        for (int j = 0; j < 16; j++) sm[e64 ^ (((j & 3) << 2) ^ (64 * j))] = v[j];
    }
    __syncthreads();
    {
        #pragma unroll
        for (int j = 0; j < 16; j++) v[j] = sm[swt + 1024 * j];
        dit4_half(v, w_t);                             // stages 10-13 ("+" half only)

        // ---- Store first LSEQ real samples, masked by pre-fetched bits ----
        #pragma unroll
        for (int j = 0; j < 8; j++) {
            int l = t + 1024 * j;
            out[(size_t)row * LSEQ + l] = (mbits >> j & 1u) ? v[j].x : 0.0f;
        }
    }
}

extern "C" void kernel_launch(void* const* d_in, const int* in_sizes, int n_in,
                              void* d_out, int out_size) {
    const float* x   = (const float*)d_in[0];
    const float* f   = (const float*)d_in[1];
    const int*   pos = (const int*)d_in[2];
    float*       out = (float*)d_out;

    const int smem_bytes = (NFFT + 1024) * sizeof(float2);   // 136 KB
    cudaFuncSetAttribute(fftconv_kernel,
                         cudaFuncAttributeMaxDynamicSharedMemorySize,
                         smem_bytes);

    fftconv_kernel<<<NROWS, NT, smem_bytes>>>(x, f, pos, out);
}